// round 10
// baseline (speedup 1.0000x reference)
#include <cuda_runtime.h>

// EMA over the innermost frames axis.
// input:         (16, 8, 256, 2048) fp32, frames contiguous
// initial_state: (16, 8, 256)       fp32
// weight:        (8, 256)           fp32   (clamped to [0,1])
// out:           (16, 8, 256, 2048) fp32
//
// R10: exact R2 winner structure (1 row/warp, lane -> contiguous float4,
// depth-2 chunk prefetch, streaming hints) + __launch_bounds__(256, 6) to
// force regs <= 40 and lift occupancy 52% -> ~70%. Evidence: DRAM% has
// tracked occ x MLP across R2/R6/R9; occupancy is the untested axis.

#define EMA_N_FRAMES 2048
#define EMA_CHUNKS   (EMA_N_FRAMES / 128)   // 16
#define EMA_WARPS_PER_BLOCK 8
#define EMA_THREADS (EMA_WARPS_PER_BLOCK * 32)

__global__ __launch_bounds__(EMA_THREADS, 6)
void ema_scan_kernel(const float* __restrict__ x,
                     const float* __restrict__ y0,
                     const float* __restrict__ wgt,
                     float* __restrict__ out,
                     int n_rows, int wgt_mod) {
    const int warp_id = blockIdx.x * EMA_WARPS_PER_BLOCK + (threadIdx.x >> 5);
    if (warp_id >= n_rows) return;            // grid divides evenly; whole warps only
    const int lane = threadIdx.x & 31;

    // per-row smoothing coefficient (uniform across the warp)
    float w = wgt[warp_id % wgt_mod];
    w = fminf(fmaxf(w, 0.0f), 1.0f);
    const float a  = 1.0f - w;
    const float a2 = a  * a;
    const float a3 = a2 * a;
    const float a4 = a2 * a2;
    float a_chunk;                            // a^128
    {
        float a8   = a4  * a4;
        float a16  = a8  * a8;
        float a32  = a16 * a16;
        float a64  = a32 * a32;
        a_chunk    = a64 * a64;
    }
    // a4^lane (decay across `lane` preceding 4-element segments)
    float a4_lane = 1.0f;
    {
        float p = a4;
        int e = lane;
        while (e) { if (e & 1) a4_lane *= p; p *= p; e >>= 1; }
    }

    const float4* __restrict__ xr =
        reinterpret_cast<const float4*>(x + (size_t)warp_id * EMA_N_FRAMES);
    float4* __restrict__ yr =
        reinterpret_cast<float4*>(out + (size_t)warp_id * EMA_N_FRAMES);

    float carry = y0[warp_id];

    // software pipeline: keep 2 chunk-loads in flight ahead of compute
    float4 b0 = __ldcs(&xr[lane]);
    float4 b1 = __ldcs(&xr[32 + lane]);

    #pragma unroll 4
    for (int c = 0; c < EMA_CHUNKS; c += 2) {
        float4 n0 = make_float4(0.f, 0.f, 0.f, 0.f);
        float4 n1 = make_float4(0.f, 0.f, 0.f, 0.f);
        if (c + 2 < EMA_CHUNKS) {
            n0 = __ldcs(&xr[(c + 2) * 32 + lane]);
            n1 = __ldcs(&xr[(c + 3) * 32 + lane]);
        }

        #pragma unroll
        for (int h = 0; h < 2; ++h) {
            float4 v = (h == 0) ? b0 : b1;

            // serial 4-element recurrence with zero incoming state
            float t0 = w * v.x;
            float t1 = fmaf(a, t0, w * v.y);
            float t2 = fmaf(a, t1, w * v.z);
            float t3 = fmaf(a, t2, w * v.w);

            // inclusive warp scan of lane-segment tails (decay a^4 per segment)
            float s  = t3;
            float pw = a4;
            #pragma unroll
            for (int off = 1; off < 32; off <<= 1) {
                float up = __shfl_up_sync(0xffffffffu, s, off);
                if (lane >= off) s = fmaf(pw, up, s);
                pw = pw * pw;
            }

            // prefix entering this lane's segment
            float excl = __shfl_up_sync(0xffffffffu, s, 1);
            float pref = (lane == 0) ? carry : fmaf(a4_lane, carry, excl);

            float4 o;
            o.x = fmaf(a,  pref, t0);
            o.y = fmaf(a2, pref, t1);
            o.z = fmaf(a3, pref, t2);
            o.w = fmaf(a4, pref, t3);
            __stcs(&yr[(c + h) * 32 + lane], o);

            float s31 = __shfl_sync(0xffffffffu, s, 31);
            carry = fmaf(a_chunk, carry, s31);
        }

        b0 = n0;
        b1 = n1;
    }
}

extern "C" void kernel_launch(void* const* d_in, const int* in_sizes, int n_in,
                              void* d_out, int out_size) {
    const float* x   = (const float*)d_in[0];   // input  (B, R, N, F)
    const float* y0  = (const float*)d_in[1];   // initial_state (B, R, N)
    const float* wgt = (const float*)d_in[2];   // weight (R, N)
    float* out = (float*)d_out;

    const int n_rows  = in_sizes[1];            // B*R*N = 32768 rows
    const int wgt_mod = in_sizes[2];            // R*N   = 2048

    const int blocks = (n_rows + EMA_WARPS_PER_BLOCK - 1) / EMA_WARPS_PER_BLOCK;
    ema_scan_kernel<<<blocks, EMA_THREADS>>>(x, y0, wgt, out, n_rows, wgt_mod);
}

// round 12
// speedup vs baseline: 1.0211x; 1.0211x over previous
#include <cuda_runtime.h>
#include <cstdint>

// EMA over the innermost frames axis.
// input:         (16, 8, 256, 2048) fp32, frames contiguous
// initial_state: (16, 8, 256)       fp32
// weight:        (8, 256)           fp32   (clamped to [0,1])
// out:           (16, 8, 256, 2048) fp32
//
// R11: cp.async (LDGSTS) smem staging. Register-resident prefetch is a dead
// end on this kernel (R2/R6/R9/R10: per-SM in-flight bytes pinned ~10KB,
// DRAM idle 19%). A 4-slot per-warp smem ring holds loads WITHOUT register
// cost: ~96KB/SM in flight, regs ~40 with no spills. cp.async.cg bypasses
// L1 (single-touch); one group per chunk; wait_group<3> before consume.
// Compute path identical to the R2 winner (warp scan, contiguous float4).

#define EMA_N_FRAMES 2048
#define EMA_CHUNKS   (EMA_N_FRAMES / 128)   // 16 chunks of 128 frames
#define EMA_WARPS_PER_BLOCK 8
#define EMA_THREADS (EMA_WARPS_PER_BLOCK * 32)
#define PIPE_D 4                            // ring depth (chunks in flight)

__global__ __launch_bounds__(EMA_THREADS)
void ema_scan_kernel(const float* __restrict__ x,
                     const float* __restrict__ y0,
                     const float* __restrict__ wgt,
                     float* __restrict__ out,
                     int n_rows, int wgt_mod) {
    __shared__ __align__(16) float4 ring[EMA_WARPS_PER_BLOCK][PIPE_D][32];

    const int wib     = threadIdx.x >> 5;                 // warp in block
    const int warp_id = blockIdx.x * EMA_WARPS_PER_BLOCK + wib;
    if (warp_id >= n_rows) return;          // grid divides evenly; whole warps only
    const int lane = threadIdx.x & 31;

    // per-row smoothing coefficient (uniform across the warp)
    float w = wgt[warp_id % wgt_mod];
    w = fminf(fmaxf(w, 0.0f), 1.0f);
    const float a  = 1.0f - w;
    const float a2 = a  * a;
    const float a3 = a2 * a;
    const float a4 = a2 * a2;
    float a_chunk;                          // a^128
    {
        float a8   = a4  * a4;
        float a16  = a8  * a8;
        float a32  = a16 * a16;
        float a64  = a32 * a32;
        a_chunk    = a64 * a64;
    }
    // a4^lane (decay across `lane` preceding 4-element segments)
    float a4_lane = 1.0f;
    {
        float p = a4;
        int e = lane;
        while (e) { if (e & 1) a4_lane *= p; p *= p; e >>= 1; }
    }

    const float4* __restrict__ xr =
        reinterpret_cast<const float4*>(x + (size_t)warp_id * EMA_N_FRAMES);
    float4* __restrict__ yr =
        reinterpret_cast<float4*>(out + (size_t)warp_id * EMA_N_FRAMES);

    // my lane's 16B target in each ring slot
    uint32_t slot_addr[PIPE_D];
    #pragma unroll
    for (int d = 0; d < PIPE_D; ++d)
        slot_addr[d] = (uint32_t)__cvta_generic_to_shared(&ring[wib][d][lane]);

    float carry = y0[warp_id];

    // prologue: fill the ring — one commit group per chunk
    #pragma unroll
    for (int d = 0; d < PIPE_D; ++d) {
        const float4* src = &xr[d * 32 + lane];
        asm volatile("cp.async.cg.shared.global [%0], [%1], 16;\n"
                     "cp.async.commit_group;\n"
                     :: "r"(slot_addr[d]), "l"(src) : "memory");
    }

    #pragma unroll 4
    for (int c = 0; c < EMA_CHUNKS; ++c) {
        // groups pending after this wait: <= PIPE_D-1  => chunk c's group done
        asm volatile("cp.async.wait_group %0;" :: "n"(PIPE_D - 1) : "memory");
        __syncwarp();

        float4 v = ring[wib][c & (PIPE_D - 1)][lane];

        // serial 4-element recurrence with zero incoming state
        float t0 = w * v.x;
        float t1 = fmaf(a, t0, w * v.y);
        float t2 = fmaf(a, t1, w * v.z);
        float t3 = fmaf(a, t2, w * v.w);

        // inclusive warp scan of lane-segment tails (decay a^4 per segment)
        float s  = t3;
        float pw = a4;
        #pragma unroll
        for (int off = 1; off < 32; off <<= 1) {
            float up = __shfl_up_sync(0xffffffffu, s, off);
            if (lane >= off) s = fmaf(pw, up, s);
            pw = pw * pw;
        }

        // prefix entering this lane's segment
        float excl = __shfl_up_sync(0xffffffffu, s, 1);
        float pref = (lane == 0) ? carry : fmaf(a4_lane, carry, excl);

        float4 o;
        o.x = fmaf(a,  pref, t0);
        o.y = fmaf(a2, pref, t1);
        o.z = fmaf(a3, pref, t2);
        o.w = fmaf(a4, pref, t3);
        __stcs(&yr[c * 32 + lane], o);

        float s31 = __shfl_sync(0xffffffffu, s, 31);
        carry = fmaf(a_chunk, carry, s31);

        // refill the slot just consumed (each lane overwrites only its own
        // 16B, already read into v). Always commit so group count advances.
        __syncwarp();
        if (c + PIPE_D < EMA_CHUNKS) {
            const float4* src = &xr[(c + PIPE_D) * 32 + lane];
            asm volatile("cp.async.cg.shared.global [%0], [%1], 16;"
                         :: "r"(slot_addr[c & (PIPE_D - 1)]), "l"(src) : "memory");
        }
        asm volatile("cp.async.commit_group;" ::: "memory");
    }
}

extern "C" void kernel_launch(void* const* d_in, const int* in_sizes, int n_in,
                              void* d_out, int out_size) {
    const float* x   = (const float*)d_in[0];   // input  (B, R, N, F)
    const float* y0  = (const float*)d_in[1];   // initial_state (B, R, N)
    const float* wgt = (const float*)d_in[2];   // weight (R, N)
    float* out = (float*)d_out;

    const int n_rows  = in_sizes[1];            // B*R*N = 32768 rows
    const int wgt_mod = in_sizes[2];            // R*N   = 2048

    const int blocks = (n_rows + EMA_WARPS_PER_BLOCK - 1) / EMA_WARPS_PER_BLOCK;
    ema_scan_kernel<<<blocks, EMA_THREADS>>>(x, y0, wgt, out, n_rows, wgt_mod);
}

// round 13
// speedup vs baseline: 1.0293x; 1.0080x over previous
#include <cuda_runtime.h>

// EMA over the innermost frames axis.
// input:         (16, 8, 256, 2048) fp32, frames contiguous
// initial_state: (16, 8, 256)       fp32
// weight:        (8, 256)           fp32   (clamped to [0,1])
// out:           (16, 8, 256, 2048) fp32
//
// R13: exact R2 winner structure (1 row/warp, lane -> contiguous float4,
// depth-2 register prefetch, __ldcs loads) but DEFAULT stores instead of
// __stcs. Evidence: 7 structures all plateau at DRAM 76-81% regardless of
// occ/MLP; in-flight bytes already exceed the BW-latency product, so the
// residual DRAM idle is read/write turnaround. Evict-first stores force
// premature small-burst L2 drains; default STG lets L2 batch write runs.

#define EMA_N_FRAMES 2048
#define EMA_CHUNKS   (EMA_N_FRAMES / 128)   // 16
#define EMA_WARPS_PER_BLOCK 8
#define EMA_THREADS (EMA_WARPS_PER_BLOCK * 32)

struct EmaCoef {
    float w, a, a2, a3, a4, a_chunk, a4_lane;
};

// Process one 128-frame chunk held as a per-lane float4. Returns new carry.
__device__ __forceinline__ float ema_chunk(float4 v, float4* __restrict__ dst,
                                           float carry, const EmaCoef& k,
                                           int lane) {
    // serial 4-element recurrence with zero incoming state
    float t0 = k.w * v.x;
    float t1 = fmaf(k.a, t0, k.w * v.y);
    float t2 = fmaf(k.a, t1, k.w * v.z);
    float t3 = fmaf(k.a, t2, k.w * v.w);

    // inclusive warp scan of lane-segment tails (decay a^4 per segment)
    float s  = t3;
    float pw = k.a4;
    #pragma unroll
    for (int off = 1; off < 32; off <<= 1) {
        float up = __shfl_up_sync(0xffffffffu, s, off);
        if (lane >= off) s = fmaf(pw, up, s);
        pw = pw * pw;
    }

    // prefix entering this lane's segment: exclusive scan + decayed carry
    float excl = __shfl_up_sync(0xffffffffu, s, 1);
    float pref = (lane == 0) ? carry : fmaf(k.a4_lane, carry, excl);

    float4 o;
    o.x = fmaf(k.a,  pref, t0);
    o.y = fmaf(k.a2, pref, t1);
    o.z = fmaf(k.a3, pref, t2);
    o.w = fmaf(k.a4, pref, t3);
    *dst = o;                 // default store: let L2 batch the write stream

    float s31 = __shfl_sync(0xffffffffu, s, 31);
    return fmaf(k.a_chunk, carry, s31);
}

__global__ __launch_bounds__(EMA_THREADS)
void ema_scan_kernel(const float* __restrict__ x,
                     const float* __restrict__ y0,
                     const float* __restrict__ wgt,
                     float* __restrict__ out,
                     int n_rows, int wgt_mod) {
    const int warp_id = blockIdx.x * EMA_WARPS_PER_BLOCK + (threadIdx.x >> 5);
    if (warp_id >= n_rows) return;            // grid divides evenly; whole warps only
    const int lane = threadIdx.x & 31;

    // per-row smoothing coefficient (uniform across the warp)
    float w = wgt[warp_id % wgt_mod];
    w = fminf(fmaxf(w, 0.0f), 1.0f);

    EmaCoef k;
    k.w  = w;
    k.a  = 1.0f - w;
    k.a2 = k.a * k.a;
    k.a3 = k.a2 * k.a;
    k.a4 = k.a2 * k.a2;
    {
        float a8   = k.a4 * k.a4;
        float a16  = a8   * a8;
        float a32  = a16  * a16;
        float a64  = a32  * a32;
        k.a_chunk  = a64  * a64;      // a^128
    }
    // a4^lane (decay across `lane` preceding 4-element segments)
    {
        float p = k.a4, r = 1.0f;
        int e = lane;
        while (e) { if (e & 1) r *= p; p *= p; e >>= 1; }
        k.a4_lane = r;
    }

    const float4* __restrict__ xr =
        reinterpret_cast<const float4*>(x + (size_t)warp_id * EMA_N_FRAMES);
    float4* __restrict__ yr =
        reinterpret_cast<float4*>(out + (size_t)warp_id * EMA_N_FRAMES);

    float carry = y0[warp_id];

    // software pipeline: keep 2 chunk-loads in flight ahead of compute
    float4 b0 = __ldcs(&xr[lane]);
    float4 b1 = __ldcs(&xr[32 + lane]);

    #pragma unroll
    for (int c = 0; c < EMA_CHUNKS; c += 2) {
        float4 n0 = make_float4(0.f, 0.f, 0.f, 0.f);
        float4 n1 = make_float4(0.f, 0.f, 0.f, 0.f);
        if (c + 2 < EMA_CHUNKS) {
            n0 = __ldcs(&xr[(c + 2) * 32 + lane]);
            n1 = __ldcs(&xr[(c + 3) * 32 + lane]);
        }
        carry = ema_chunk(b0, &yr[c * 32 + lane],       carry, k, lane);
        carry = ema_chunk(b1, &yr[(c + 1) * 32 + lane], carry, k, lane);
        b0 = n0;
        b1 = n1;
    }
}

extern "C" void kernel_launch(void* const* d_in, const int* in_sizes, int n_in,
                              void* d_out, int out_size) {
    const float* x   = (const float*)d_in[0];   // input  (B, R, N, F)
    const float* y0  = (const float*)d_in[1];   // initial_state (B, R, N)
    const float* wgt = (const float*)d_in[2];   // weight (R, N)
    float* out = (float*)d_out;

    const int n_rows  = in_sizes[1];            // B*R*N = 32768 rows
    const int wgt_mod = in_sizes[2];            // R*N   = 2048

    const int blocks = (n_rows + EMA_WARPS_PER_BLOCK - 1) / EMA_WARPS_PER_BLOCK;
    ema_scan_kernel<<<blocks, EMA_THREADS>>>(x, y0, wgt, out, n_rows, wgt_mod);
}

// round 17
// speedup vs baseline: 1.0554x; 1.0254x over previous
#include <cuda_runtime.h>

// EMA over the innermost frames axis.
// input:         (16, 8, 256, 2048) fp32, frames contiguous
// initial_state: (16, 8, 256)       fp32
// weight:        (8, 256)           fp32   (clamped to [0,1])
// out:           (16, 8, 256, 2048) fp32
//
// R14 (resubmit; prior rounds hit broker flakes): warp-local smem
// transpose. Evidence: DRAM pinned 76-81% across 8 structures regardless
// of occ/MLP; binder hypothesis is the per-byte serial SHFL chain.
// Chunk = 512 frames: 4 coalesced LDG.128 -> swizzled smem -> each lane
// takes 16 CONSECUTIVE frames -> ONE warp scan per 512 frames (4x fewer
// than R2) -> outputs back through smem -> coalesced __stcs.
// Swizzle u^((u>>2)&7) on float4 units: conflict-free in both access
// patterns (verified per 8-lane phase). All sync is __syncwarp.

#define EMA_N_FRAMES 2048
#define EMA_WARPS_PER_BLOCK 8
#define EMA_THREADS (EMA_WARPS_PER_BLOCK * 32)
#define UNITS 128                 // float4 units per 512-frame chunk
#define NCHUNK (EMA_N_FRAMES / 512)   // 4

__device__ __forceinline__ int swz(int u) { return u ^ ((u >> 2) & 7); }

__global__ __launch_bounds__(EMA_THREADS)
void ema_scan_kernel(const float* __restrict__ x,
                     const float* __restrict__ y0,
                     const float* __restrict__ wgt,
                     float* __restrict__ out,
                     int n_rows, int wgt_mod) {
    __shared__ __align__(16) float4 buf[EMA_WARPS_PER_BLOCK][UNITS];

    const int wib     = threadIdx.x >> 5;
    const int warp_id = blockIdx.x * EMA_WARPS_PER_BLOCK + wib;
    if (warp_id >= n_rows) return;        // whole warps only
    const int lane = threadIdx.x & 31;

    float w = wgt[warp_id % wgt_mod];
    w = fminf(fmaxf(w, 0.0f), 1.0f);
    const float a  = 1.0f - w;
    const float a2 = a  * a;
    const float a3 = a2 * a;
    const float a4 = a2 * a2;
    const float a8  = a4 * a4;
    const float a16 = a8 * a8;
    float a512;
    {
        float a32  = a16  * a16;
        float a64  = a32  * a32;
        float a128 = a64  * a64;
        float a256 = a128 * a128;
        a512       = a256 * a256;
    }
    // a16^lane: decay across `lane` preceding 16-frame segments
    float a16_lane = 1.0f;
    {
        float p = a16;
        int e = lane;
        while (e) { if (e & 1) a16_lane *= p; p *= p; e >>= 1; }
    }

    const float4* __restrict__ xr =
        reinterpret_cast<const float4*>(x + (size_t)warp_id * EMA_N_FRAMES);
    float4* __restrict__ yr =
        reinterpret_cast<float4*>(out + (size_t)warp_id * EMA_N_FRAMES);

    float carry = y0[warp_id];

    // prologue: chunk 0 in registers
    float4 g0 = __ldcs(&xr[lane]);
    float4 g1 = __ldcs(&xr[32 + lane]);
    float4 g2 = __ldcs(&xr[64 + lane]);
    float4 g3 = __ldcs(&xr[96 + lane]);

    #pragma unroll
    for (int k = 0; k < NCHUNK; ++k) {
        // stage current chunk into swizzled smem
        buf[wib][swz(lane)]      = g0;
        buf[wib][swz(32 + lane)] = g1;
        buf[wib][swz(64 + lane)] = g2;
        buf[wib][swz(96 + lane)] = g3;

        // prefetch next chunk while we compute this one
        if (k + 1 < NCHUNK) {
            const int b = (k + 1) * UNITS + lane;
            g0 = __ldcs(&xr[b]);
            g1 = __ldcs(&xr[b + 32]);
            g2 = __ldcs(&xr[b + 64]);
            g3 = __ldcs(&xr[b + 96]);
        }
        __syncwarp();

        // transposed read: lane owns frames [16*lane, 16*lane+16)
        float4 v0 = buf[wib][swz(4 * lane + 0)];
        float4 v1 = buf[wib][swz(4 * lane + 1)];
        float4 v2 = buf[wib][swz(4 * lane + 2)];
        float4 v3 = buf[wib][swz(4 * lane + 3)];

        // serial 16-element recurrence with zero incoming state
        float t0  = w * v0.x;
        float t1  = fmaf(a, t0,  w * v0.y);
        float t2  = fmaf(a, t1,  w * v0.z);
        float t3  = fmaf(a, t2,  w * v0.w);
        float t4  = fmaf(a, t3,  w * v1.x);
        float t5  = fmaf(a, t4,  w * v1.y);
        float t6  = fmaf(a, t5,  w * v1.z);
        float t7  = fmaf(a, t6,  w * v1.w);
        float t8  = fmaf(a, t7,  w * v2.x);
        float t9  = fmaf(a, t8,  w * v2.y);
        float t10 = fmaf(a, t9,  w * v2.z);
        float t11 = fmaf(a, t10, w * v2.w);
        float t12 = fmaf(a, t11, w * v3.x);
        float t13 = fmaf(a, t12, w * v3.y);
        float t14 = fmaf(a, t13, w * v3.z);
        float t15 = fmaf(a, t14, w * v3.w);

        // ONE inclusive warp scan over 32 segments (decay a^16 per segment)
        float s  = t15;
        float pw = a16;
        #pragma unroll
        for (int off = 1; off < 32; off <<= 1) {
            float up = __shfl_up_sync(0xffffffffu, s, off);
            if (lane >= off) s = fmaf(pw, up, s);
            pw = pw * pw;
        }

        float excl = __shfl_up_sync(0xffffffffu, s, 1);
        float pref = (lane == 0) ? carry : fmaf(a16_lane, carry, excl);

        // apply: o_i = t_i + a^{i+1} * pref   (4 short chains via a4 jumps)
        float q0 = pref * a;
        float q1 = pref * a2;
        float q2 = pref * a3;
        float q3 = pref * a4;
        t0  += q0;  t1  += q1;  t2  += q2;  t3  += q3;
        q0 *= a4;   q1 *= a4;   q2 *= a4;   q3 *= a4;
        t4  += q0;  t5  += q1;  t6  += q2;  t7  += q3;
        q0 *= a4;   q1 *= a4;   q2 *= a4;   q3 *= a4;
        t8  += q0;  t9  += q1;  t10 += q2;  t11 += q3;
        q0 *= a4;   q1 *= a4;   q2 *= a4;   q3 *= a4;
        t12 += q0;  t13 += q1;  t14 += q2;  t15 += q3;

        // write outputs back to the SAME lane-private region (no hazard)
        buf[wib][swz(4 * lane + 0)] = make_float4(t0,  t1,  t2,  t3);
        buf[wib][swz(4 * lane + 1)] = make_float4(t4,  t5,  t6,  t7);
        buf[wib][swz(4 * lane + 2)] = make_float4(t8,  t9,  t10, t11);
        buf[wib][swz(4 * lane + 3)] = make_float4(t12, t13, t14, t15);
        __syncwarp();

        // coalesced write-out
        const int ob = k * UNITS + lane;
        __stcs(&yr[ob],      buf[wib][swz(lane)]);
        __stcs(&yr[ob + 32], buf[wib][swz(32 + lane)]);
        __stcs(&yr[ob + 64], buf[wib][swz(64 + lane)]);
        __stcs(&yr[ob + 96], buf[wib][swz(96 + lane)]);

        // carry = y at last frame of this chunk
        float s31 = __shfl_sync(0xffffffffu, s, 31);
        carry = fmaf(a512, carry, s31);

        __syncwarp();   // buffer reads done before next iteration's STS
    }
}

extern "C" void kernel_launch(void* const* d_in, const int* in_sizes, int n_in,
                              void* d_out, int out_size) {
    const float* x   = (const float*)d_in[0];   // input  (B, R, N, F)
    const float* y0  = (const float*)d_in[1];   // initial_state (B, R, N)
    const float* wgt = (const float*)d_in[2];   // weight (R, N)
    float* out = (float*)d_out;

    const int n_rows  = in_sizes[1];            // B*R*N = 32768 rows
    const int wgt_mod = in_sizes[2];            // R*N   = 2048

    const int blocks = (n_rows + EMA_WARPS_PER_BLOCK - 1) / EMA_WARPS_PER_BLOCK;
    ema_scan_kernel<<<blocks, EMA_THREADS>>>(x, y0, wgt, out, n_rows, wgt_mod);
}